// round 2
// baseline (speedup 1.0000x reference)
#include <cuda_runtime.h>
#include <math.h>

// ---------------- problem constants (fixed by setup_inputs) ----------------
#define NV    50000      // vertices
#define INDIM 256        // input features
#define HC    256        // H*C
#define HN    8          // heads
#define CN    32         // channels per head
#define EN    10000      // hyperedges
#define NNZ   320000     // incidence entries
#define NEG_SLOPE 0.2f

// ---------------- scratch (device globals; no allocation allowed) ----------
__device__ __align__(16) float g_X0[NV * HC];    // X @ W^T
__device__ __align__(16) float g_Xe[EN * HC];    // per-edge mean features
__device__ __align__(16) float g_alpha[EN * HN]; // per-edge attention logits
__device__ int   g_ecnt[EN];
__device__ int   g_eoff[EN + 1];
__device__ int   g_ecur[EN];
__device__ int   g_vcnt[NV];
__device__ int   g_voff[NV + 1];
__device__ int   g_vcur[NV];
__device__ int   g_ecsr[NNZ];            // vertices grouped by edge
__device__ int   g_vcsr[NNZ];            // edges grouped by vertex

// ---------------- CSR construction ----------------
__global__ void zero_counts_kernel() {
    int i = blockIdx.x * blockDim.x + threadIdx.x;
    if (i < NV) g_vcnt[i] = 0;
    if (i < EN) g_ecnt[i] = 0;
}

__global__ void hist_kernel(const int* __restrict__ vertex,
                            const int* __restrict__ edges) {
    int j = blockIdx.x * blockDim.x + threadIdx.x;
    if (j >= NNZ) return;
    atomicAdd(&g_ecnt[edges[j]], 1);
    atomicAdd(&g_vcnt[vertex[j]], 1);
}

// single-block exclusive scan; which==0 -> edges, which==1 -> vertices
__global__ void scan_kernel(int which) {
    const int* cnt; int* off; int* cur; int n;
    if (which == 0) { cnt = g_ecnt; off = g_eoff; cur = g_ecur; n = EN; }
    else            { cnt = g_vcnt; off = g_voff; cur = g_vcur; n = NV; }

    __shared__ int part[1024];
    const int T = 1024;
    int tid = threadIdx.x;
    int chunk = (n + T - 1) / T;
    int beg = tid * chunk;
    int end = beg + chunk;
    if (beg > n) beg = n;
    if (end > n) end = n;

    int s = 0;
    for (int i = beg; i < end; i++) s += cnt[i];
    part[tid] = s;
    __syncthreads();
    // inclusive Hillis-Steele on partials
    for (int d = 1; d < T; d <<= 1) {
        int v = (tid >= d) ? part[tid - d] : 0;
        __syncthreads();
        part[tid] += v;
        __syncthreads();
    }
    int run = (tid == 0) ? 0 : part[tid - 1];
    for (int i = beg; i < end; i++) {
        off[i] = run; cur[i] = run;
        run += cnt[i];
    }
    if (tid == T - 1) off[n] = run;
}

__global__ void scatter_kernel(const int* __restrict__ vertex,
                               const int* __restrict__ edges) {
    int j = blockIdx.x * blockDim.x + threadIdx.x;
    if (j >= NNZ) return;
    int e = edges[j];
    int v = vertex[j];
    int pe = atomicAdd(&g_ecur[e], 1);
    g_ecsr[pe] = v;
    int pv = atomicAdd(&g_vcur[v], 1);
    g_vcsr[pv] = e;
}

// ---------------- GEMM: X0[m,n] = sum_k X[m,k] * W[n,k] ----------------
// 128x64 block tile, BK=16, 8x4 per-thread micro-tile, k-major smem (+4 pad
// keeps 16-byte alignment for float4 compute loads).
#define BM 128
#define BN 64
#define BK 16
#define LDA (BM + 4)
#define LDB (BN + 4)

__global__ __launch_bounds__(256) void gemm_kernel(const float* __restrict__ A,
                                                   const float* __restrict__ B) {
    __shared__ __align__(16) float As[BK * LDA];
    __shared__ __align__(16) float Bs[BK * LDB];

    const int m0 = blockIdx.x * BM;
    const int n0 = blockIdx.y * BN;
    const int tid = threadIdx.x;
    const int tx = tid & 15;     // 16 col-groups of 4
    const int ty = tid >> 4;     // 16 row-groups of 8

    float acc[8][4];
    #pragma unroll
    for (int i = 0; i < 8; i++)
        #pragma unroll
        for (int j = 0; j < 4; j++) acc[i][j] = 0.f;

    for (int k0 = 0; k0 < INDIM; k0 += BK) {
        // A tile: 128 rows x 16 k -> 512 float4, 2 per thread (transposed store)
        #pragma unroll
        for (int li = 0; li < 2; li++) {
            int idx = tid + li * 256;
            int r = idx >> 2, q = idx & 3;
            float4 v = make_float4(0.f, 0.f, 0.f, 0.f);
            if (m0 + r < NV)
                v = *(const float4*)&A[(size_t)(m0 + r) * INDIM + k0 + q * 4];
            As[(q * 4 + 0) * LDA + r] = v.x;
            As[(q * 4 + 1) * LDA + r] = v.y;
            As[(q * 4 + 2) * LDA + r] = v.z;
            As[(q * 4 + 3) * LDA + r] = v.w;
        }
        // B tile: 64 rows x 16 k -> 256 float4, 1 per thread
        {
            int r = tid >> 2, q = tid & 3;
            float4 v = *(const float4*)&B[(size_t)(n0 + r) * INDIM + k0 + q * 4];
            Bs[(q * 4 + 0) * LDB + r] = v.x;
            Bs[(q * 4 + 1) * LDB + r] = v.y;
            Bs[(q * 4 + 2) * LDB + r] = v.z;
            Bs[(q * 4 + 3) * LDB + r] = v.w;
        }
        __syncthreads();

        #pragma unroll
        for (int kk = 0; kk < BK; kk++) {
            float4 a0 = *(const float4*)&As[kk * LDA + ty * 8];
            float4 a1 = *(const float4*)&As[kk * LDA + ty * 8 + 4];
            float4 b0 = *(const float4*)&Bs[kk * LDB + tx * 4];
            float av[8] = {a0.x, a0.y, a0.z, a0.w, a1.x, a1.y, a1.z, a1.w};
            float bv[4] = {b0.x, b0.y, b0.z, b0.w};
            #pragma unroll
            for (int i = 0; i < 8; i++)
                #pragma unroll
                for (int j = 0; j < 4; j++)
                    acc[i][j] = fmaf(av[i], bv[j], acc[i][j]);
        }
        __syncthreads();
    }

    #pragma unroll
    for (int i = 0; i < 8; i++) {
        int m = m0 + ty * 8 + i;
        if (m < NV) {
            float4 o = make_float4(acc[i][0], acc[i][1], acc[i][2], acc[i][3]);
            *(float4*)&g_X0[(size_t)m * HC + n0 + tx * 4] = o;
        }
    }
}

// ---------------- per-hyperedge mean + attention logits ----------------
// 1 block (256 threads) per hyperedge; thread t owns channel t (= h*32+c).
__global__ __launch_bounds__(256) void edge_agg_kernel(const float* __restrict__ att) {
    int e = blockIdx.x;
    int t = threadIdx.x;
    int b = g_eoff[e];
    int d = g_eoff[e + 1] - b;

    float s = 0.f;
    for (int i = 0; i < d; i++) {
        int v = g_ecsr[b + i];
        s += g_X0[(size_t)v * HC + t];
    }
    float mean = s / (float)(d > 0 ? d : 1);
    g_Xe[(size_t)e * HC + t] = mean;

    float p = mean * att[t];
    #pragma unroll
    for (int o = 16; o > 0; o >>= 1)
        p += __shfl_down_sync(0xffffffffu, p, o);
    if ((t & 31) == 0)
        g_alpha[e * HN + (t >> 5)] = p;
}

// ---------------- per-vertex: softmax + weighted sum + row l2-norm ----------
// 1 warp per vertex. Lane l owns channel c=l across all 8 heads.
__global__ __launch_bounds__(256) void vertex_kernel(float* __restrict__ out) {
    int warp = (blockIdx.x * blockDim.x + threadIdx.x) >> 5;
    if (warp >= NV) return;
    int l  = threadIdx.x & 31;
    int hh = l & 7;                 // head this lane tracks (replicated x4)
    int b = g_voff[warp];
    int d = g_voff[warp + 1] - b;

    // pass 1: segment max of leaky_relu(alpha) per head
    float amax = -INFINITY;
    for (int i = 0; i < d; i++) {
        int e = g_vcsr[b + i];
        float a = g_alpha[e * HN + hh];
        a = a > 0.f ? a : NEG_SLOPE * a;
        amax = fmaxf(amax, a);
    }
    amax = fmaxf(amax, __shfl_xor_sync(0xffffffffu, amax, 8));
    amax = fmaxf(amax, __shfl_xor_sync(0xffffffffu, amax, 16));

    // pass 2: exp weights, denom, weighted feature accumulation
    float acc[8];
    #pragma unroll
    for (int h = 0; h < 8; h++) acc[h] = 0.f;
    float denom = 0.f;
    for (int i = 0; i < d; i++) {
        int e = g_vcsr[b + i];
        float a = g_alpha[e * HN + hh];
        a = a > 0.f ? a : NEG_SLOPE * a;
        float w = __expf(a - amax);
        denom += w;
        const float* xr = g_Xe + (size_t)e * HC;
        #pragma unroll
        for (int h = 0; h < 8; h++) {
            float wh = __shfl_sync(0xffffffffu, w, h);
            acc[h] = fmaf(wh, xr[h * 32 + l], acc[h]);
        }
    }

    float out8[8];
    float ss = 0.f;
    #pragma unroll
    for (int h = 0; h < 8; h++) {
        float dh = __shfl_sync(0xffffffffu, denom, h);
        float o = acc[h] / (dh + 1e-16f);
        out8[h] = o;
        ss = fmaf(o, o, ss);
    }
    #pragma unroll
    for (int o = 16; o > 0; o >>= 1)
        ss += __shfl_xor_sync(0xffffffffu, ss, o);
    float scale = (ss > 0.f) ? rsqrtf(ss) : 0.f;
    #pragma unroll
    for (int h = 0; h < 8; h++)
        out[(size_t)warp * HC + h * 32 + l] = out8[h] * scale;
}

// ---------------- launch ----------------
extern "C" void kernel_launch(void* const* d_in, const int* in_sizes, int n_in,
                              void* d_out, int out_size) {
    const float* X      = (const float*)d_in[0];
    const float* W      = (const float*)d_in[1];
    const float* att    = (const float*)d_in[2];
    const int*   vertex = (const int*)d_in[3];
    const int*   edges  = (const int*)d_in[4];
    float* out = (float*)d_out;

    zero_counts_kernel<<<(NV + 255) / 256, 256>>>();
    hist_kernel<<<(NNZ + 255) / 256, 256>>>(vertex, edges);
    scan_kernel<<<1, 1024>>>(0);
    scan_kernel<<<1, 1024>>>(1);
    scatter_kernel<<<(NNZ + 255) / 256, 256>>>(vertex, edges);

    dim3 ggrid((NV + BM - 1) / BM, HC / BN);
    gemm_kernel<<<ggrid, 256>>>(X, W);

    edge_agg_kernel<<<EN, 256>>>(att);
    vertex_kernel<<<(NV * 32 + 255) / 256, 256>>>(out);
}

// round 4
// speedup vs baseline: 1.2238x; 1.2238x over previous
#include <cuda_runtime.h>
#include <math.h>

// ---------------- problem constants (fixed by setup_inputs) ----------------
#define NV    50000      // vertices
#define INDIM 256        // input features
#define HC    256        // H*C
#define HN    8          // heads
#define CN    32         // channels per head
#define EN    10000      // hyperedges
#define NNZ   320000     // incidence entries
#define NEG_SLOPE 0.2f

#define SCN (EN + NV)             // combined scan length: 60000
#define SNB ((SCN + 255) / 256)   // scan blocks: 235

// ---------------- scratch (device globals; no allocation allowed) ----------
__device__ __align__(16) float g_X0[NV * HC];    // X @ W^T
__device__ __align__(16) float g_Xe[EN * HC];    // per-edge mean features
__device__ __align__(16) float g_alpha[EN * HN]; // per-edge attention logits
__device__ int   g_ecnt[EN];
__device__ int   g_eoff[EN + 1];
__device__ int   g_ecur[EN];
__device__ int   g_vcnt[NV];
__device__ int   g_voff[NV + 1];
__device__ int   g_vcur[NV];
__device__ int   g_ecsr[NNZ];            // vertices grouped by edge
__device__ int   g_vcsr[NNZ];            // edges grouped by vertex
__device__ int   g_pscan[SCN];           // per-element inclusive scan (in-block)
__device__ int   g_bsum[SNB];            // block sums
__device__ int   g_bofs[SNB];            // exclusive scan of block sums

// ---------------- CSR construction ----------------
__global__ void zero_counts_kernel() {
    int i = blockIdx.x * blockDim.x + threadIdx.x;
    if (i < NV) g_vcnt[i] = 0;
    if (i < EN) g_ecnt[i] = 0;
}

__global__ void hist_kernel(const int* __restrict__ vertex,
                            const int* __restrict__ edges) {
    int j = blockIdx.x * blockDim.x + threadIdx.x;
    if (j >= NNZ) return;
    atomicAdd(&g_ecnt[edges[j]], 1);
    atomicAdd(&g_vcnt[vertex[j]], 1);
}

// inclusive scan of 256 values within a block (warp shuffles + smem)
__device__ __forceinline__ int block_incl_scan(int v) {
    int lane = threadIdx.x & 31;
    int wid  = threadIdx.x >> 5;
    int x = v;
    #pragma unroll
    for (int o = 1; o < 32; o <<= 1) {
        int t = __shfl_up_sync(0xffffffffu, x, o);
        if (lane >= o) x += t;
    }
    __shared__ int ws[8];
    if (lane == 31) ws[wid] = x;
    __syncthreads();
    if (wid == 0) {
        int s = (lane < 8) ? ws[lane] : 0;
        #pragma unroll
        for (int o = 1; o < 8; o <<= 1) {
            int t = __shfl_up_sync(0xffffffffu, s, o);
            if (lane >= o) s += t;
        }
        if (lane < 8) ws[lane] = s;
    }
    __syncthreads();
    return x + (wid > 0 ? ws[wid - 1] : 0);
}

// pass 1: per-block inclusive scan over combined [ecnt | vcnt]
__global__ __launch_bounds__(256) void scan1_kernel() {
    int i = blockIdx.x * 256 + threadIdx.x;
    int v = 0;
    if (i < SCN) v = (i < EN) ? g_ecnt[i] : g_vcnt[i - EN];
    int incl = block_incl_scan(v);
    if (i < SCN) g_pscan[i] = incl;
    if (threadIdx.x == 255) g_bsum[blockIdx.x] = incl;
}

// pass 2: exclusive scan of block sums (SNB <= 256)
__global__ __launch_bounds__(256) void scan2_kernel() {
    int b = threadIdx.x;
    int v = (b < SNB) ? g_bsum[b] : 0;
    int incl = block_incl_scan(v);
    if (b < SNB) g_bofs[b] = incl - v;
}

// pass 3: finalize offsets; totals of both histograms are NNZ by construction
__global__ __launch_bounds__(256) void scan3_kernel() {
    int i = blockIdx.x * 256 + threadIdx.x;
    if (i == 0) { g_eoff[EN] = NNZ; g_voff[NV] = NNZ; }
    if (i >= SCN) return;
    int cnt  = (i < EN) ? g_ecnt[i] : g_vcnt[i - EN];
    int excl = g_pscan[i] + g_bofs[i >> 8] - cnt;
    if (i < EN) {
        g_eoff[i] = excl; g_ecur[i] = excl;
    } else {
        int j = i - EN;
        int o = excl - NNZ;
        g_voff[j] = o; g_vcur[j] = o;
    }
}

__global__ void scatter_kernel(const int* __restrict__ vertex,
                               const int* __restrict__ edges) {
    int j = blockIdx.x * blockDim.x + threadIdx.x;
    if (j >= NNZ) return;
    int e = edges[j];
    int v = vertex[j];
    int pe = atomicAdd(&g_ecur[e], 1);
    g_ecsr[pe] = v;
    int pv = atomicAdd(&g_vcur[v], 1);
    g_vcsr[pv] = e;
}

// ---------------- GEMM: X0[m,n] = sum_k X[m,k] * W[n,k] ----------------
// 128x128 block tile, BK=16, 8x8 per-thread micro-tile, k-major smem.
#define BM 128
#define BN 128
#define BK 16
#define LDA (BM + 4)
#define LDB (BN + 4)

__global__ __launch_bounds__(256) void gemm_kernel(const float* __restrict__ A,
                                                   const float* __restrict__ B) {
    __shared__ __align__(16) float As[BK * LDA];
    __shared__ __align__(16) float Bs[BK * LDB];

    const int m0 = blockIdx.x * BM;
    const int n0 = blockIdx.y * BN;
    const int tid = threadIdx.x;
    const int tx = tid & 15;     // 16 col-groups of 8
    const int ty = tid >> 4;     // 16 row-groups of 8

    float acc[8][8];
    #pragma unroll
    for (int i = 0; i < 8; i++)
        #pragma unroll
        for (int j = 0; j < 8; j++) acc[i][j] = 0.f;

    for (int k0 = 0; k0 < INDIM; k0 += BK) {
        // A tile: 128 rows x 16 k -> 512 float4, 2 per thread (transposed store)
        #pragma unroll
        for (int li = 0; li < 2; li++) {
            int idx = tid + li * 256;
            int r = idx >> 2, q = idx & 3;
            float4 v = make_float4(0.f, 0.f, 0.f, 0.f);
            if (m0 + r < NV)
                v = *(const float4*)&A[(size_t)(m0 + r) * INDIM + k0 + q * 4];
            As[(q * 4 + 0) * LDA + r] = v.x;
            As[(q * 4 + 1) * LDA + r] = v.y;
            As[(q * 4 + 2) * LDA + r] = v.z;
            As[(q * 4 + 3) * LDA + r] = v.w;
        }
        // B tile: 128 rows x 16 k -> 512 float4, 2 per thread
        #pragma unroll
        for (int li = 0; li < 2; li++) {
            int idx = tid + li * 256;
            int r = idx >> 2, q = idx & 3;
            float4 v = *(const float4*)&B[(size_t)(n0 + r) * INDIM + k0 + q * 4];
            Bs[(q * 4 + 0) * LDB + r] = v.x;
            Bs[(q * 4 + 1) * LDB + r] = v.y;
            Bs[(q * 4 + 2) * LDB + r] = v.z;
            Bs[(q * 4 + 3) * LDB + r] = v.w;
        }
        __syncthreads();

        #pragma unroll
        for (int kk = 0; kk < BK; kk++) {
            float4 a0 = *(const float4*)&As[kk * LDA + ty * 8];
            float4 a1 = *(const float4*)&As[kk * LDA + ty * 8 + 4];
            float4 b0 = *(const float4*)&Bs[kk * LDB + tx * 8];
            float4 b1 = *(const float4*)&Bs[kk * LDB + tx * 8 + 4];
            float av[8] = {a0.x, a0.y, a0.z, a0.w, a1.x, a1.y, a1.z, a1.w};
            float bv[8] = {b0.x, b0.y, b0.z, b0.w, b1.x, b1.y, b1.z, b1.w};
            #pragma unroll
            for (int i = 0; i < 8; i++)
                #pragma unroll
                for (int j = 0; j < 8; j++)
                    acc[i][j] = fmaf(av[i], bv[j], acc[i][j]);
        }
        __syncthreads();
    }

    #pragma unroll
    for (int i = 0; i < 8; i++) {
        int m = m0 + ty * 8 + i;
        if (m < NV) {
            float4 o0 = make_float4(acc[i][0], acc[i][1], acc[i][2], acc[i][3]);
            float4 o1 = make_float4(acc[i][4], acc[i][5], acc[i][6], acc[i][7]);
            *(float4*)&g_X0[(size_t)m * HC + n0 + tx * 8]     = o0;
            *(float4*)&g_X0[(size_t)m * HC + n0 + tx * 8 + 4] = o1;
        }
    }
}

// ---------------- per-hyperedge mean + attention logits ----------------
// 1 block (256 threads) per hyperedge; thread t owns channel t (= h*32+c).
__global__ __launch_bounds__(256) void edge_agg_kernel(const float* __restrict__ att) {
    int e = blockIdx.x;
    int t = threadIdx.x;
    int b = g_eoff[e];
    int d = g_eoff[e + 1] - b;

    float s = 0.f;
    for (int i = 0; i < d; i++) {
        int v = g_ecsr[b + i];
        s += g_X0[(size_t)v * HC + t];
    }
    float mean = s / (float)(d > 0 ? d : 1);
    g_Xe[(size_t)e * HC + t] = mean;

    float p = mean * att[t];
    #pragma unroll
    for (int o = 16; o > 0; o >>= 1)
        p += __shfl_down_sync(0xffffffffu, p, o);
    if ((t & 31) == 0)
        g_alpha[e * HN + (t >> 5)] = p;
}

// ---------------- per-vertex: softmax + weighted sum + row l2-norm ----------
// 1 warp per vertex. Lane l owns channel c=l across all 8 heads.
__global__ __launch_bounds__(256) void vertex_kernel(float* __restrict__ out) {
    int warp = (blockIdx.x * blockDim.x + threadIdx.x) >> 5;
    if (warp >= NV) return;
    int l  = threadIdx.x & 31;
    int hh = l & 7;                 // head this lane tracks (replicated x4)
    int b = g_voff[warp];
    int d = g_voff[warp + 1] - b;

    // pass 1: segment max of leaky_relu(alpha) per head
    float amax = -INFINITY;
    for (int i = 0; i < d; i++) {
        int e = g_vcsr[b + i];
        float a = g_alpha[e * HN + hh];
        a = a > 0.f ? a : NEG_SLOPE * a;
        amax = fmaxf(amax, a);
    }
    amax = fmaxf(amax, __shfl_xor_sync(0xffffffffu, amax, 8));
    amax = fmaxf(amax, __shfl_xor_sync(0xffffffffu, amax, 16));

    // pass 2: exp weights, denom, weighted feature accumulation
    float acc[8];
    #pragma unroll
    for (int h = 0; h < 8; h++) acc[h] = 0.f;
    float denom = 0.f;
    for (int i = 0; i < d; i++) {
        int e = g_vcsr[b + i];
        float a = g_alpha[e * HN + hh];
        a = a > 0.f ? a : NEG_SLOPE * a;
        float w = __expf(a - amax);
        denom += w;
        const float* xr = g_Xe + (size_t)e * HC;
        #pragma unroll
        for (int h = 0; h < 8; h++) {
            float wh = __shfl_sync(0xffffffffu, w, h);
            acc[h] = fmaf(wh, xr[h * 32 + l], acc[h]);
        }
    }

    float out8[8];
    float ss = 0.f;
    #pragma unroll
    for (int h = 0; h < 8; h++) {
        float dh = __shfl_sync(0xffffffffu, denom, h);
        float o = acc[h] / (dh + 1e-16f);
        out8[h] = o;
        ss = fmaf(o, o, ss);
    }
    #pragma unroll
    for (int o = 16; o > 0; o >>= 1)
        ss += __shfl_xor_sync(0xffffffffu, ss, o);
    float scale = (ss > 0.f) ? rsqrtf(ss) : 0.f;
    #pragma unroll
    for (int h = 0; h < 8; h++)
        out[(size_t)warp * HC + h * 32 + l] = out8[h] * scale;
}

// ---------------- launch ----------------
extern "C" void kernel_launch(void* const* d_in, const int* in_sizes, int n_in,
                              void* d_out, int out_size) {
    const float* X      = (const float*)d_in[0];
    const float* W      = (const float*)d_in[1];
    const float* att    = (const float*)d_in[2];
    const int*   vertex = (const int*)d_in[3];
    const int*   edges  = (const int*)d_in[4];
    float* out = (float*)d_out;

    zero_counts_kernel<<<(NV + 255) / 256, 256>>>();
    hist_kernel<<<(NNZ + 255) / 256, 256>>>(vertex, edges);
    scan1_kernel<<<SNB, 256>>>();
    scan2_kernel<<<1, 256>>>();
    scan3_kernel<<<SNB, 256>>>();
    scatter_kernel<<<(NNZ + 255) / 256, 256>>>(vertex, edges);

    dim3 ggrid((NV + BM - 1) / BM, HC / BN);
    gemm_kernel<<<ggrid, 256>>>(X, W);

    edge_agg_kernel<<<EN, 256>>>(att);
    vertex_kernel<<<(NV * 32 + 255) / 256, 256>>>(out);
}

// round 6
// speedup vs baseline: 1.7771x; 1.4521x over previous
#include <cuda_runtime.h>
#include <cuda_bf16.h>
#include <math.h>
#include <cstdint>

// ---------------- problem constants (fixed by setup_inputs) ----------------
#define NV    50000      // vertices
#define INDIM 256        // input features
#define HC    256        // H*C
#define HN    8          // heads
#define CN    32         // channels per head
#define EN    10000      // hyperedges
#define NNZ   320000     // incidence entries
#define NEG_SLOPE 0.2f

#define SCN (EN + NV)             // combined scan length: 60000
#define SNB ((SCN + 255) / 256)   // scan blocks: 235

// ---------------- scratch (device globals; no allocation allowed) ----------
__device__ __align__(16) float g_X0[NV * HC];    // X @ W^T
__device__ __align__(16) float g_Xe[EN * HC];    // per-edge mean features
__device__ __align__(16) float g_alpha[EN * HN]; // per-edge attention logits
__device__ __align__(16) __nv_bfloat16 g_Whi[HC * INDIM];
__device__ __align__(16) __nv_bfloat16 g_Wlo[HC * INDIM];
__device__ int   g_ecnt[EN];
__device__ int   g_eoff[EN + 1];
__device__ int   g_ecur[EN];
__device__ int   g_vcnt[NV];
__device__ int   g_voff[NV + 1];
__device__ int   g_vcur[NV];
__device__ int   g_ecsr[NNZ];            // vertices grouped by edge
__device__ int   g_vcsr[NNZ];            // edges grouped by vertex
__device__ int   g_pscan[SCN];           // per-element inclusive scan (in-block)
__device__ int   g_bsum[SNB];            // block sums
__device__ int   g_bofs[SNB];            // exclusive scan of block sums

// ---------------- CSR construction ----------------
__global__ void zero_counts_kernel() {
    int i = blockIdx.x * blockDim.x + threadIdx.x;
    if (i < NV) g_vcnt[i] = 0;
    if (i < EN) g_ecnt[i] = 0;
}

__global__ void hist_kernel(const int* __restrict__ vertex,
                            const int* __restrict__ edges) {
    int j = blockIdx.x * blockDim.x + threadIdx.x;
    if (j >= NNZ) return;
    atomicAdd(&g_ecnt[edges[j]], 1);
    atomicAdd(&g_vcnt[vertex[j]], 1);
}

__device__ __forceinline__ int block_incl_scan(int v) {
    int lane = threadIdx.x & 31;
    int wid  = threadIdx.x >> 5;
    int x = v;
    #pragma unroll
    for (int o = 1; o < 32; o <<= 1) {
        int t = __shfl_up_sync(0xffffffffu, x, o);
        if (lane >= o) x += t;
    }
    __shared__ int ws[8];
    if (lane == 31) ws[wid] = x;
    __syncthreads();
    if (wid == 0) {
        int s = (lane < 8) ? ws[lane] : 0;
        #pragma unroll
        for (int o = 1; o < 8; o <<= 1) {
            int t = __shfl_up_sync(0xffffffffu, s, o);
            if (lane >= o) s += t;
        }
        if (lane < 8) ws[lane] = s;
    }
    __syncthreads();
    return x + (wid > 0 ? ws[wid - 1] : 0);
}

__global__ __launch_bounds__(256) void scan1_kernel() {
    int i = blockIdx.x * 256 + threadIdx.x;
    int v = 0;
    if (i < SCN) v = (i < EN) ? g_ecnt[i] : g_vcnt[i - EN];
    int incl = block_incl_scan(v);
    if (i < SCN) g_pscan[i] = incl;
    if (threadIdx.x == 255) g_bsum[blockIdx.x] = incl;
}

__global__ __launch_bounds__(256) void scan2_kernel() {
    int b = threadIdx.x;
    int v = (b < SNB) ? g_bsum[b] : 0;
    int incl = block_incl_scan(v);
    if (b < SNB) g_bofs[b] = incl - v;
}

__global__ __launch_bounds__(256) void scan3_kernel() {
    int i = blockIdx.x * 256 + threadIdx.x;
    if (i == 0) { g_eoff[EN] = NNZ; g_voff[NV] = NNZ; }
    if (i >= SCN) return;
    int cnt  = (i < EN) ? g_ecnt[i] : g_vcnt[i - EN];
    int excl = g_pscan[i] + g_bofs[i >> 8] - cnt;
    if (i < EN) {
        g_eoff[i] = excl; g_ecur[i] = excl;
    } else {
        int j = i - EN;
        int o = excl - NNZ;
        g_voff[j] = o; g_vcur[j] = o;
    }
}

__global__ void scatter_kernel(const int* __restrict__ vertex,
                               const int* __restrict__ edges) {
    int j = blockIdx.x * blockDim.x + threadIdx.x;
    if (j >= NNZ) return;
    int e = edges[j];
    int v = vertex[j];
    int pe = atomicAdd(&g_ecur[e], 1);
    g_ecsr[pe] = v;
    int pv = atomicAdd(&g_vcur[v], 1);
    g_vcsr[pv] = e;
}

// ---------------- W -> bf16 hi/lo ----------------
__global__ __launch_bounds__(256) void wconv_kernel(const float* __restrict__ W) {
    int i = blockIdx.x * 256 + threadIdx.x;  // HC*INDIM = 65536
    float v = W[i];
    __nv_bfloat16 h = __float2bfloat16(v);
    g_Whi[i] = h;
    g_Wlo[i] = __float2bfloat16(v - __bfloat162float(h));
}

// ---------------- HMMA GEMM: X0 = X @ W^T via 3xBF16 split --------------
// Block 128x128, 8 warps (2M x 4N), warp tile 64x32, m16n8k16 bf16 mma.sync.
#define BK 32
#define LDS_K (BK + 8)   // bf16 elements per smem row (pad -> conflict-free)

__device__ __forceinline__ void mma_bf16(float* c, const uint32_t* a, const uint32_t* b) {
    asm volatile(
        "mma.sync.aligned.m16n8k16.row.col.f32.bf16.bf16.f32 "
        "{%0,%1,%2,%3}, {%4,%5,%6,%7}, {%8,%9}, {%0,%1,%2,%3};"
        : "+f"(c[0]), "+f"(c[1]), "+f"(c[2]), "+f"(c[3])
        : "r"(a[0]), "r"(a[1]), "r"(a[2]), "r"(a[3]), "r"(b[0]), "r"(b[1]));
}

__device__ __forceinline__ uint32_t pack2(__nv_bfloat16 a, __nv_bfloat16 b) {
    return ((uint32_t)__bfloat16_as_ushort(b) << 16) | (uint32_t)__bfloat16_as_ushort(a);
}

__global__ __launch_bounds__(256) void gemm_mma_kernel(const float* __restrict__ X) {
    __shared__ __align__(16) __nv_bfloat16 AsH[128 * LDS_K];
    __shared__ __align__(16) __nv_bfloat16 AsL[128 * LDS_K];
    __shared__ __align__(16) __nv_bfloat16 BsH[128 * LDS_K];
    __shared__ __align__(16) __nv_bfloat16 BsL[128 * LDS_K];

    const int tid  = threadIdx.x;
    const int lane = tid & 31;
    const int wid  = tid >> 5;
    const int wM   = wid >> 2;        // 0..1 -> 64-row slab
    const int wN   = wid & 3;         // 0..3 -> 32-col slab
    const int m0   = blockIdx.x * 128;
    const int n0   = blockIdx.y * 128;
    const int g    = lane >> 2;       // 0..7
    const int qc   = (lane & 3) * 2;  // 0,2,4,6

    float acc[4][4][4];
    #pragma unroll
    for (int a = 0; a < 4; a++)
        #pragma unroll
        for (int b = 0; b < 4; b++)
            #pragma unroll
            for (int c = 0; c < 4; c++) acc[a][b][c] = 0.f;

    for (int kb = 0; kb < INDIM; kb += BK) {
        // ---- A chunk: 128 rows x 32 k fp32 -> bf16 hi/lo in smem ----
        #pragma unroll
        for (int it = 0; it < 4; it++) {
            int idx = tid + it * 256;          // 0..1023 float4s
            int r = idx >> 3, q = idx & 7;     // 8 float4 per row
            int m = m0 + r;
            float4 v = make_float4(0.f, 0.f, 0.f, 0.f);
            if (m < NV)
                v = *(const float4*)&X[(size_t)m * INDIM + kb + q * 4];
            __nv_bfloat16 h0 = __float2bfloat16(v.x);
            __nv_bfloat16 h1 = __float2bfloat16(v.y);
            __nv_bfloat16 h2 = __float2bfloat16(v.z);
            __nv_bfloat16 h3 = __float2bfloat16(v.w);
            __nv_bfloat16 l0 = __float2bfloat16(v.x - __bfloat162float(h0));
            __nv_bfloat16 l1 = __float2bfloat16(v.y - __bfloat162float(h1));
            __nv_bfloat16 l2 = __float2bfloat16(v.z - __bfloat162float(h2));
            __nv_bfloat16 l3 = __float2bfloat16(v.w - __bfloat162float(h3));
            *(uint2*)&AsH[r * LDS_K + q * 4] = make_uint2(pack2(h0, h1), pack2(h2, h3));
            *(uint2*)&AsL[r * LDS_K + q * 4] = make_uint2(pack2(l0, l1), pack2(l2, l3));
        }
        // ---- B chunk: 128 n-rows x 32 k bf16 hi/lo (already split) ----
        #pragma unroll
        for (int it = 0; it < 2; it++) {
            int idx = tid + it * 256;          // 0..511 uint4s (8 bf16 each)
            int r = idx >> 2, q = idx & 3;
            size_t src = (size_t)(n0 + r) * INDIM + kb + q * 8;
            *(uint4*)&BsH[r * LDS_K + q * 8] = *(const uint4*)&g_Whi[src];
            *(uint4*)&BsL[r * LDS_K + q * 8] = *(const uint4*)&g_Wlo[src];
        }
        __syncthreads();

        #pragma unroll
        for (int kk = 0; kk < 2; kk++) {
            int k0 = kk * 16;
            uint32_t aH[4][4], aL[4][4], bH[4][2], bL[4][2];
            #pragma unroll
            for (int tm = 0; tm < 4; tm++) {
                int r0 = wM * 64 + tm * 16 + g;
                aH[tm][0] = *(const uint32_t*)&AsH[r0 * LDS_K + k0 + qc];
                aH[tm][1] = *(const uint32_t*)&AsH[(r0 + 8) * LDS_K + k0 + qc];
                aH[tm][2] = *(const uint32_t*)&AsH[r0 * LDS_K + k0 + qc + 8];
                aH[tm][3] = *(const uint32_t*)&AsH[(r0 + 8) * LDS_K + k0 + qc + 8];
                aL[tm][0] = *(const uint32_t*)&AsL[r0 * LDS_K + k0 + qc];
                aL[tm][1] = *(const uint32_t*)&AsL[(r0 + 8) * LDS_K + k0 + qc];
                aL[tm][2] = *(const uint32_t*)&AsL[r0 * LDS_K + k0 + qc + 8];
                aL[tm][3] = *(const uint32_t*)&AsL[(r0 + 8) * LDS_K + k0 + qc + 8];
            }
            #pragma unroll
            for (int tn = 0; tn < 4; tn++) {
                int nn = wN * 32 + tn * 8 + g;
                bH[tn][0] = *(const uint32_t*)&BsH[nn * LDS_K + k0 + qc];
                bH[tn][1] = *(const uint32_t*)&BsH[nn * LDS_K + k0 + qc + 8];
                bL[tn][0] = *(const uint32_t*)&BsL[nn * LDS_K + k0 + qc];
                bL[tn][1] = *(const uint32_t*)&BsL[nn * LDS_K + k0 + qc + 8];
            }
            #pragma unroll
            for (int tm = 0; tm < 4; tm++)
                #pragma unroll
                for (int tn = 0; tn < 4; tn++) {
                    mma_bf16(acc[tm][tn], aH[tm], bH[tn]);
                    mma_bf16(acc[tm][tn], aH[tm], bL[tn]);
                    mma_bf16(acc[tm][tn], aL[tm], bH[tn]);
                }
        }
        __syncthreads();
    }

    // ---- store C fragments ----
    #pragma unroll
    for (int tm = 0; tm < 4; tm++) {
        int r0 = m0 + wM * 64 + tm * 16 + g;
        #pragma unroll
        for (int tn = 0; tn < 4; tn++) {
            int col = n0 + wN * 32 + tn * 8 + qc;
            if (r0 < NV)
                *(float2*)&g_X0[(size_t)r0 * HC + col] =
                    make_float2(acc[tm][tn][0], acc[tm][tn][1]);
            if (r0 + 8 < NV)
                *(float2*)&g_X0[(size_t)(r0 + 8) * HC + col] =
                    make_float2(acc[tm][tn][2], acc[tm][tn][3]);
        }
    }
}

// ---------------- per-hyperedge mean + attention logits ----------------
__global__ __launch_bounds__(256) void edge_agg_kernel(const float* __restrict__ att) {
    int e = blockIdx.x;
    int t = threadIdx.x;
    int b = g_eoff[e];
    int d = g_eoff[e + 1] - b;

    float s = 0.f;
    for (int i = 0; i < d; i++) {
        int v = g_ecsr[b + i];
        s += g_X0[(size_t)v * HC + t];
    }
    float mean = s / (float)(d > 0 ? d : 1);
    g_Xe[(size_t)e * HC + t] = mean;

    float p = mean * att[t];
    #pragma unroll
    for (int o = 16; o > 0; o >>= 1)
        p += __shfl_down_sync(0xffffffffu, p, o);
    if ((t & 31) == 0)
        g_alpha[e * HN + (t >> 5)] = p;
}

// ---------------- per-vertex: softmax + weighted sum + row l2-norm ----------
__global__ __launch_bounds__(256) void vertex_kernel(float* __restrict__ out) {
    int warp = (blockIdx.x * blockDim.x + threadIdx.x) >> 5;
    if (warp >= NV) return;
    int l  = threadIdx.x & 31;
    int hh = l & 7;
    int b = g_voff[warp];
    int d = g_voff[warp + 1] - b;

    float amax = -INFINITY;
    for (int i = 0; i < d; i++) {
        int e = g_vcsr[b + i];
        float a = g_alpha[e * HN + hh];
        a = a > 0.f ? a : NEG_SLOPE * a;
        amax = fmaxf(amax, a);
    }
    amax = fmaxf(amax, __shfl_xor_sync(0xffffffffu, amax, 8));
    amax = fmaxf(amax, __shfl_xor_sync(0xffffffffu, amax, 16));

    float acc[8];
    #pragma unroll
    for (int h = 0; h < 8; h++) acc[h] = 0.f;
    float denom = 0.f;
    for (int i = 0; i < d; i++) {
        int e = g_vcsr[b + i];
        float a = g_alpha[e * HN + hh];
        a = a > 0.f ? a : NEG_SLOPE * a;
        float w = __expf(a - amax);
        denom += w;
        const float* xr = g_Xe + (size_t)e * HC;
        #pragma unroll
        for (int h = 0; h < 8; h++) {
            float wh = __shfl_sync(0xffffffffu, w, h);
            acc[h] = fmaf(wh, xr[h * 32 + l], acc[h]);
        }
    }

    float out8[8];
    float ss = 0.f;
    #pragma unroll
    for (int h = 0; h < 8; h++) {
        float dh = __shfl_sync(0xffffffffu, denom, h);
        float o = acc[h] / (dh + 1e-16f);
        out8[h] = o;
        ss = fmaf(o, o, ss);
    }
    #pragma unroll
    for (int o = 16; o > 0; o >>= 1)
        ss += __shfl_xor_sync(0xffffffffu, ss, o);
    float scale = (ss > 0.f) ? rsqrtf(ss) : 0.f;
    #pragma unroll
    for (int h = 0; h < 8; h++)
        out[(size_t)warp * HC + h * 32 + l] = out8[h] * scale;
}

// ---------------- launch ----------------
extern "C" void kernel_launch(void* const* d_in, const int* in_sizes, int n_in,
                              void* d_out, int out_size) {
    const float* X      = (const float*)d_in[0];
    const float* W      = (const float*)d_in[1];
    const float* att    = (const float*)d_in[2];
    const int*   vertex = (const int*)d_in[3];
    const int*   edges  = (const int*)d_in[4];
    float* out = (float*)d_out;

    zero_counts_kernel<<<(NV + 255) / 256, 256>>>();
    hist_kernel<<<(NNZ + 255) / 256, 256>>>(vertex, edges);
    scan1_kernel<<<SNB, 256>>>();
    scan2_kernel<<<1, 256>>>();
    scan3_kernel<<<SNB, 256>>>();
    scatter_kernel<<<(NNZ + 255) / 256, 256>>>(vertex, edges);

    wconv_kernel<<<(HC * INDIM) / 256, 256>>>(W);
    dim3 ggrid((NV + 127) / 128, HC / 128);
    gemm_mma_kernel<<<ggrid, 256>>>(X);

    edge_agg_kernel<<<EN, 256>>>(att);
    vertex_kernel<<<(NV * 32 + 255) / 256, 256>>>(out);
}

// round 7
// speedup vs baseline: 2.3178x; 1.3043x over previous
#include <cuda_runtime.h>
#include <cuda_bf16.h>
#include <math.h>
#include <cstdint>

// ---------------- problem constants (fixed by setup_inputs) ----------------
#define NV    50000      // vertices
#define INDIM 256        // input features
#define HC    256        // H*C
#define HN    8          // heads
#define CN    32         // channels per head
#define EN    10000      // hyperedges
#define NNZ   320000     // incidence entries
#define NEG_SLOPE 0.2f

#define SCN (EN + NV)             // combined scan length: 60000
#define SNB ((SCN + 255) / 256)   // scan blocks: 235

// ---------------- scratch (device globals; no allocation allowed) ----------
__device__ __align__(16) float g_Xagg[EN * INDIM];  // per-edge mean of X rows
__device__ __align__(16) float g_Xe[EN * HC];       // Xagg @ W^T
__device__ __align__(16) float g_alpha[EN * HN];    // attention logits
__device__ __align__(16) __nv_bfloat16 g_Whi[HC * INDIM];
__device__ __align__(16) __nv_bfloat16 g_Wlo[HC * INDIM];
__device__ int   g_ecnt[EN];
__device__ int   g_eoff[EN + 1];
__device__ int   g_ecur[EN];
__device__ int   g_vcnt[NV];
__device__ int   g_voff[NV + 1];
__device__ int   g_vcur[NV];
__device__ int   g_ecsr[NNZ];            // vertices grouped by edge
__device__ int   g_vcsr[NNZ];            // edges grouped by vertex
__device__ int   g_pscan[SCN];
__device__ int   g_bsum[SNB];
__device__ int   g_bofs[SNB];

// ---------------- CSR construction ----------------
__global__ void zero_counts_kernel() {
    int i = blockIdx.x * blockDim.x + threadIdx.x;
    if (i < NV) g_vcnt[i] = 0;
    if (i < EN) g_ecnt[i] = 0;
}

__global__ void hist_kernel(const int* __restrict__ vertex,
                            const int* __restrict__ edges) {
    int j = blockIdx.x * blockDim.x + threadIdx.x;
    if (j >= NNZ) return;
    atomicAdd(&g_ecnt[edges[j]], 1);
    atomicAdd(&g_vcnt[vertex[j]], 1);
}

__device__ __forceinline__ int block_incl_scan(int v) {
    int lane = threadIdx.x & 31;
    int wid  = threadIdx.x >> 5;
    int x = v;
    #pragma unroll
    for (int o = 1; o < 32; o <<= 1) {
        int t = __shfl_up_sync(0xffffffffu, x, o);
        if (lane >= o) x += t;
    }
    __shared__ int ws[8];
    if (lane == 31) ws[wid] = x;
    __syncthreads();
    if (wid == 0) {
        int s = (lane < 8) ? ws[lane] : 0;
        #pragma unroll
        for (int o = 1; o < 8; o <<= 1) {
            int t = __shfl_up_sync(0xffffffffu, s, o);
            if (lane >= o) s += t;
        }
        if (lane < 8) ws[lane] = s;
    }
    __syncthreads();
    return x + (wid > 0 ? ws[wid - 1] : 0);
}

__global__ __launch_bounds__(256) void scan1_kernel() {
    int i = blockIdx.x * 256 + threadIdx.x;
    int v = 0;
    if (i < SCN) v = (i < EN) ? g_ecnt[i] : g_vcnt[i - EN];
    int incl = block_incl_scan(v);
    if (i < SCN) g_pscan[i] = incl;
    if (threadIdx.x == 255) g_bsum[blockIdx.x] = incl;
}

__global__ __launch_bounds__(256) void scan2_kernel() {
    int b = threadIdx.x;
    int v = (b < SNB) ? g_bsum[b] : 0;
    int incl = block_incl_scan(v);
    if (b < SNB) g_bofs[b] = incl - v;
}

__global__ __launch_bounds__(256) void scan3_kernel() {
    int i = blockIdx.x * 256 + threadIdx.x;
    if (i == 0) { g_eoff[EN] = NNZ; g_voff[NV] = NNZ; }
    if (i >= SCN) return;
    int cnt  = (i < EN) ? g_ecnt[i] : g_vcnt[i - EN];
    int excl = g_pscan[i] + g_bofs[i >> 8] - cnt;
    if (i < EN) {
        g_eoff[i] = excl; g_ecur[i] = excl;
    } else {
        int j = i - EN;
        int o = excl - NNZ;
        g_voff[j] = o; g_vcur[j] = o;
    }
}

__global__ void scatter_kernel(const int* __restrict__ vertex,
                               const int* __restrict__ edges) {
    int j = blockIdx.x * blockDim.x + threadIdx.x;
    if (j >= NNZ) return;
    int e = edges[j];
    int v = vertex[j];
    int pe = atomicAdd(&g_ecur[e], 1);
    g_ecsr[pe] = v;
    int pv = atomicAdd(&g_vcur[v], 1);
    g_vcsr[pv] = e;
}

// ---------------- W -> bf16 hi/lo ----------------
__global__ __launch_bounds__(256) void wconv_kernel(const float* __restrict__ W) {
    int i = blockIdx.x * 256 + threadIdx.x;  // HC*INDIM = 65536
    float v = W[i];
    __nv_bfloat16 h = __float2bfloat16(v);
    g_Whi[i] = h;
    g_Wlo[i] = __float2bfloat16(v - __bfloat162float(h));
}

// ---------------- input-space edge mean: Xagg[e] = mean_{v in e} X[v] -----
// 1 block (256 threads) per edge; thread t owns input feature t.
__global__ __launch_bounds__(256) void agg_kernel(const float* __restrict__ X) {
    int e = blockIdx.x;
    int t = threadIdx.x;
    int b = g_eoff[e];
    int d = g_eoff[e + 1] - b;

    float s = 0.f;
    for (int i = 0; i < d; i++) {
        int v = g_ecsr[b + i];
        s += X[(size_t)v * INDIM + t];
    }
    g_Xagg[(size_t)e * INDIM + t] = s / (float)(d > 0 ? d : 1);
}

// ---------------- HMMA GEMM: Xe = Xagg @ W^T via 3xBF16 split ------------
// Block 128x128, 8 warps (2M x 4N), warp tile 64x32, m16n8k16 bf16 mma.sync.
#define BK 32
#define LDS_K (BK + 8)

__device__ __forceinline__ void mma_bf16(float* c, const uint32_t* a, const uint32_t* b) {
    asm volatile(
        "mma.sync.aligned.m16n8k16.row.col.f32.bf16.bf16.f32 "
        "{%0,%1,%2,%3}, {%4,%5,%6,%7}, {%8,%9}, {%0,%1,%2,%3};"
        : "+f"(c[0]), "+f"(c[1]), "+f"(c[2]), "+f"(c[3])
        : "r"(a[0]), "r"(a[1]), "r"(a[2]), "r"(a[3]), "r"(b[0]), "r"(b[1]));
}

__device__ __forceinline__ uint32_t pack2(__nv_bfloat16 a, __nv_bfloat16 b) {
    return ((uint32_t)__bfloat16_as_ushort(b) << 16) | (uint32_t)__bfloat16_as_ushort(a);
}

__global__ __launch_bounds__(256) void gemm_mma_kernel() {
    __shared__ __align__(16) __nv_bfloat16 AsH[128 * LDS_K];
    __shared__ __align__(16) __nv_bfloat16 AsL[128 * LDS_K];
    __shared__ __align__(16) __nv_bfloat16 BsH[128 * LDS_K];
    __shared__ __align__(16) __nv_bfloat16 BsL[128 * LDS_K];

    const int tid  = threadIdx.x;
    const int lane = tid & 31;
    const int wid  = tid >> 5;
    const int wM   = wid >> 2;
    const int wN   = wid & 3;
    const int m0   = blockIdx.x * 128;
    const int n0   = blockIdx.y * 128;
    const int g    = lane >> 2;
    const int qc   = (lane & 3) * 2;

    float acc[4][4][4];
    #pragma unroll
    for (int a = 0; a < 4; a++)
        #pragma unroll
        for (int b = 0; b < 4; b++)
            #pragma unroll
            for (int c = 0; c < 4; c++) acc[a][b][c] = 0.f;

    for (int kb = 0; kb < INDIM; kb += BK) {
        #pragma unroll
        for (int it = 0; it < 4; it++) {
            int idx = tid + it * 256;
            int r = idx >> 3, q = idx & 7;
            int m = m0 + r;
            float4 v = make_float4(0.f, 0.f, 0.f, 0.f);
            if (m < EN)
                v = *(const float4*)&g_Xagg[(size_t)m * INDIM + kb + q * 4];
            __nv_bfloat16 h0 = __float2bfloat16(v.x);
            __nv_bfloat16 h1 = __float2bfloat16(v.y);
            __nv_bfloat16 h2 = __float2bfloat16(v.z);
            __nv_bfloat16 h3 = __float2bfloat16(v.w);
            __nv_bfloat16 l0 = __float2bfloat16(v.x - __bfloat162float(h0));
            __nv_bfloat16 l1 = __float2bfloat16(v.y - __bfloat162float(h1));
            __nv_bfloat16 l2 = __float2bfloat16(v.z - __bfloat162float(h2));
            __nv_bfloat16 l3 = __float2bfloat16(v.w - __bfloat162float(h3));
            *(uint2*)&AsH[r * LDS_K + q * 4] = make_uint2(pack2(h0, h1), pack2(h2, h3));
            *(uint2*)&AsL[r * LDS_K + q * 4] = make_uint2(pack2(l0, l1), pack2(l2, l3));
        }
        #pragma unroll
        for (int it = 0; it < 2; it++) {
            int idx = tid + it * 256;
            int r = idx >> 2, q = idx & 3;
            size_t src = (size_t)(n0 + r) * INDIM + kb + q * 8;
            *(uint4*)&BsH[r * LDS_K + q * 8] = *(const uint4*)&g_Whi[src];
            *(uint4*)&BsL[r * LDS_K + q * 8] = *(const uint4*)&g_Wlo[src];
        }
        __syncthreads();

        #pragma unroll
        for (int kk = 0; kk < 2; kk++) {
            int k0 = kk * 16;
            uint32_t aH[4][4], aL[4][4], bH[4][2], bL[4][2];
            #pragma unroll
            for (int tm = 0; tm < 4; tm++) {
                int r0 = wM * 64 + tm * 16 + g;
                aH[tm][0] = *(const uint32_t*)&AsH[r0 * LDS_K + k0 + qc];
                aH[tm][1] = *(const uint32_t*)&AsH[(r0 + 8) * LDS_K + k0 + qc];
                aH[tm][2] = *(const uint32_t*)&AsH[r0 * LDS_K + k0 + qc + 8];
                aH[tm][3] = *(const uint32_t*)&AsH[(r0 + 8) * LDS_K + k0 + qc + 8];
                aL[tm][0] = *(const uint32_t*)&AsL[r0 * LDS_K + k0 + qc];
                aL[tm][1] = *(const uint32_t*)&AsL[(r0 + 8) * LDS_K + k0 + qc];
                aL[tm][2] = *(const uint32_t*)&AsL[r0 * LDS_K + k0 + qc + 8];
                aL[tm][3] = *(const uint32_t*)&AsL[(r0 + 8) * LDS_K + k0 + qc + 8];
            }
            #pragma unroll
            for (int tn = 0; tn < 4; tn++) {
                int nn = wN * 32 + tn * 8 + g;
                bH[tn][0] = *(const uint32_t*)&BsH[nn * LDS_K + k0 + qc];
                bH[tn][1] = *(const uint32_t*)&BsH[nn * LDS_K + k0 + qc + 8];
                bL[tn][0] = *(const uint32_t*)&BsL[nn * LDS_K + k0 + qc];
                bL[tn][1] = *(const uint32_t*)&BsL[nn * LDS_K + k0 + qc + 8];
            }
            #pragma unroll
            for (int tm = 0; tm < 4; tm++)
                #pragma unroll
                for (int tn = 0; tn < 4; tn++) {
                    mma_bf16(acc[tm][tn], aH[tm], bH[tn]);
                    mma_bf16(acc[tm][tn], aH[tm], bL[tn]);
                    mma_bf16(acc[tm][tn], aL[tm], bH[tn]);
                }
        }
        __syncthreads();
    }

    #pragma unroll
    for (int tm = 0; tm < 4; tm++) {
        int r0 = m0 + wM * 64 + tm * 16 + g;
        #pragma unroll
        for (int tn = 0; tn < 4; tn++) {
            int col = n0 + wN * 32 + tn * 8 + qc;
            if (r0 < EN)
                *(float2*)&g_Xe[(size_t)r0 * HC + col] =
                    make_float2(acc[tm][tn][0], acc[tm][tn][1]);
            if (r0 + 8 < EN)
                *(float2*)&g_Xe[(size_t)(r0 + 8) * HC + col] =
                    make_float2(acc[tm][tn][2], acc[tm][tn][3]);
        }
    }
}

// ---------------- per-edge attention logits ----------------
// 1 block (256 threads) per edge; warp w reduces head w's 32 channels.
__global__ __launch_bounds__(256) void alpha_kernel(const float* __restrict__ att) {
    int e = blockIdx.x;
    int t = threadIdx.x;
    float p = g_Xe[(size_t)e * HC + t] * att[t];
    #pragma unroll
    for (int o = 16; o > 0; o >>= 1)
        p += __shfl_down_sync(0xffffffffu, p, o);
    if ((t & 31) == 0)
        g_alpha[e * HN + (t >> 5)] = p;
}

// ---------------- per-vertex: softmax + weighted sum + row l2-norm ----------
__global__ __launch_bounds__(256) void vertex_kernel(float* __restrict__ out) {
    int warp = (blockIdx.x * blockDim.x + threadIdx.x) >> 5;
    if (warp >= NV) return;
    int l  = threadIdx.x & 31;
    int hh = l & 7;
    int b = g_voff[warp];
    int d = g_voff[warp + 1] - b;

    float amax = -INFINITY;
    for (int i = 0; i < d; i++) {
        int e = g_vcsr[b + i];
        float a = g_alpha[e * HN + hh];
        a = a > 0.f ? a : NEG_SLOPE * a;
        amax = fmaxf(amax, a);
    }
    amax = fmaxf(amax, __shfl_xor_sync(0xffffffffu, amax, 8));
    amax = fmaxf(amax, __shfl_xor_sync(0xffffffffu, amax, 16));

    float acc[8];
    #pragma unroll
    for (int h = 0; h < 8; h++) acc[h] = 0.f;
    float denom = 0.f;
    for (int i = 0; i < d; i++) {
        int e = g_vcsr[b + i];
        float a = g_alpha[e * HN + hh];
        a = a > 0.f ? a : NEG_SLOPE * a;
        float w = __expf(a - amax);
        denom += w;
        const float* xr = g_Xe + (size_t)e * HC;
        #pragma unroll
        for (int h = 0; h < 8; h++) {
            float wh = __shfl_sync(0xffffffffu, w, h);
            acc[h] = fmaf(wh, xr[h * 32 + l], acc[h]);
        }
    }

    float out8[8];
    float ss = 0.f;
    #pragma unroll
    for (int h = 0; h < 8; h++) {
        float dh = __shfl_sync(0xffffffffu, denom, h);
        float o = acc[h] / (dh + 1e-16f);
        out8[h] = o;
        ss = fmaf(o, o, ss);
    }
    #pragma unroll
    for (int o = 16; o > 0; o >>= 1)
        ss += __shfl_xor_sync(0xffffffffu, ss, o);
    float scale = (ss > 0.f) ? rsqrtf(ss) : 0.f;
    #pragma unroll
    for (int h = 0; h < 8; h++)
        out[(size_t)warp * HC + h * 32 + l] = out8[h] * scale;
}

// ---------------- launch ----------------
extern "C" void kernel_launch(void* const* d_in, const int* in_sizes, int n_in,
                              void* d_out, int out_size) {
    const float* X      = (const float*)d_in[0];
    const float* W      = (const float*)d_in[1];
    const float* att    = (const float*)d_in[2];
    const int*   vertex = (const int*)d_in[3];
    const int*   edges  = (const int*)d_in[4];
    float* out = (float*)d_out;

    zero_counts_kernel<<<(NV + 255) / 256, 256>>>();
    hist_kernel<<<(NNZ + 255) / 256, 256>>>(vertex, edges);
    scan1_kernel<<<SNB, 256>>>();
    scan2_kernel<<<1, 256>>>();
    scan3_kernel<<<SNB, 256>>>();
    scatter_kernel<<<(NNZ + 255) / 256, 256>>>(vertex, edges);

    wconv_kernel<<<(HC * INDIM) / 256, 256>>>(W);
    agg_kernel<<<EN, 256>>>(X);
    dim3 ggrid((EN + 127) / 128, HC / 128);
    gemm_mma_kernel<<<ggrid, 256>>>();

    alpha_kernel<<<EN, 256>>>(att);
    vertex_kernel<<<(NV * 32 + 255) / 256, 256>>>(out);
}